// round 2
// baseline (speedup 1.0000x reference)
#include <cuda_runtime.h>
#include <math.h>
#include <stdint.h>

// Problem constants
#define NB   2
#define SEQ  2048
#define HID  4096
#define NH   32
#define NKV  8
#define HD   128
#define QKVO ((NH + 2*NKV)*HD)   // 6144
#define MTOK (NB*SEQ)            // 4096

// Scratch (no cudaMalloc allowed)
__device__ float g_qkv[(size_t)MTOK * QKVO];          // 96 MB
__device__ float g_q[(size_t)NB * NH * SEQ * HD];     // 64 MB
__device__ float g_k[(size_t)NB * NKV * SEQ * HD];    // 16 MB
__device__ float g_v[(size_t)NB * NKV * SEQ * HD];    // 16 MB
__device__ float g_attn[(size_t)MTOK * HID];          // 64 MB

// ---------------------------------------------------------------------------
// GEMM-NT: C[M,N] = A[M,K] * W[N,K]^T   (both operands K-major, fp32)
// 128x128 tile, BK=16, 256 threads, 8x8 per-thread micro-tile.
// M % 128 == 0, N % 128 == 0, K % 16 == 0 guaranteed by problem shapes.
// ---------------------------------------------------------------------------
#define BM 128
#define BN 128
#define BK 16

__global__ void __launch_bounds__(256) gemm_nt_kernel(
    const float* __restrict__ A, const float* __restrict__ W,
    float* __restrict__ C, int M, int N, int K)
{
    __shared__ float As[BK][BM + 4];
    __shared__ float Bs[BK][BN + 4];

    const int tid = threadIdx.x;
    const int bm = blockIdx.y * BM;
    const int bn = blockIdx.x * BN;
    const int tm = tid >> 4;      // 0..15
    const int tn = tid & 15;      // 0..15

    float acc[8][8];
#pragma unroll
    for (int i = 0; i < 8; i++)
#pragma unroll
        for (int j = 0; j < 8; j++) acc[i][j] = 0.f;

    const int lrow = tid >> 2;        // 0..63
    const int lcol = (tid & 3) * 4;   // 0,4,8,12

    for (int k0 = 0; k0 < K; k0 += BK) {
#pragma unroll
        for (int r = 0; r < 2; r++) {
            const int row = lrow + r * 64;
            float4 va = *(const float4*)(A + (size_t)(bm + row) * K + k0 + lcol);
            As[lcol + 0][row] = va.x; As[lcol + 1][row] = va.y;
            As[lcol + 2][row] = va.z; As[lcol + 3][row] = va.w;
            float4 vb = *(const float4*)(W + (size_t)(bn + row) * K + k0 + lcol);
            Bs[lcol + 0][row] = vb.x; Bs[lcol + 1][row] = vb.y;
            Bs[lcol + 2][row] = vb.z; Bs[lcol + 3][row] = vb.w;
        }
        __syncthreads();
#pragma unroll
        for (int k = 0; k < BK; k++) {
            float a[8], b[8];
            *(float4*)(a)     = *(const float4*)&As[k][tm * 8];
            *(float4*)(a + 4) = *(const float4*)&As[k][tm * 8 + 4];
            *(float4*)(b)     = *(const float4*)&Bs[k][tn * 8];
            *(float4*)(b + 4) = *(const float4*)&Bs[k][tn * 8 + 4];
#pragma unroll
            for (int i = 0; i < 8; i++)
#pragma unroll
                for (int j = 0; j < 8; j++)
                    acc[i][j] += a[i] * b[j];
        }
        __syncthreads();
    }

#pragma unroll
    for (int i = 0; i < 8; i++) {
        float* cp = C + (size_t)(bm + tm * 8 + i) * N + bn + tn * 8;
        float4 o0 = make_float4(acc[i][0], acc[i][1], acc[i][2], acc[i][3]);
        float4 o1 = make_float4(acc[i][4], acc[i][5], acc[i][6], acc[i][7]);
        *(float4*)cp = o0;
        *(float4*)(cp + 4) = o1;
    }
}

// ---------------------------------------------------------------------------
// Per-head RMSNorm + RoPE, scatter to head-major q/k/v buffers.
// grid = (B*S, 48): head 0..31 -> q, 32..39 -> k, 40..47 -> v (copy only).
// 128 threads = head_dim.
// ---------------------------------------------------------------------------
__global__ void __launch_bounds__(128) norm_rope_kernel(
    const float* __restrict__ qkv, const int* __restrict__ positions,
    const float* __restrict__ qw, const float* __restrict__ kw,
    float* __restrict__ gq, float* __restrict__ gk, float* __restrict__ gv)
{
    const int token = blockIdx.x;           // 0..B*S-1
    const int b = token / SEQ;
    const int s = token - b * SEQ;
    const int head = blockIdx.y;            // 0..47
    const int d = threadIdx.x;              // 0..127

    if (head >= NH + NKV) {                 // V head: plain copy (block-uniform branch)
        const int kvh = head - NH - NKV;
        float x = qkv[(size_t)token * QKVO + (size_t)(NH + NKV) * HD + kvh * HD + d];
        gv[((size_t)(b * NKV + kvh) * SEQ + s) * HD + d] = x;
        return;
    }

    const bool is_q = head < NH;
    const float* src = qkv + (size_t)token * QKVO
                     + (is_q ? (size_t)head * HD : (size_t)NH * HD + (size_t)(head - NH) * HD);
    float x = src[d];

    __shared__ float red[4];
    __shared__ float ys[HD];

    float sq = x * x;
#pragma unroll
    for (int o = 16; o > 0; o >>= 1) sq += __shfl_xor_sync(0xffffffffu, sq, o);
    if ((d & 31) == 0) red[d >> 5] = sq;
    __syncthreads();
    const float var = (red[0] + red[1] + red[2] + red[3]) * (1.0f / HD);
    const float rn = rsqrtf(var + 1e-6f);
    const float w = is_q ? qw[d] : kw[d];
    ys[d] = x * rn * w;
    __syncthreads();

    const int pos = positions[s];
    const int i = d & 63;
    // inv_freq = 10000^(-i/64); compute angle in double for accuracy
    const double inv = exp(-(double)i * (9.210340371976184 / 64.0));
    const double ang = (double)pos * inv;
    double sd, cd;
    sincos(ang, &sd, &cd);
    const float c = (float)cd, sn = (float)sd;

    const float x1 = ys[i];
    const float x2 = ys[i + 64];
    const float outv = (d < 64) ? (x1 * c - x2 * sn) : (x2 * c + x1 * sn);

    if (is_q)
        gq[((size_t)(b * NH + head) * SEQ + s) * HD + d] = outv;
    else
        gk[((size_t)(b * NKV + (head - NH)) * SEQ + s) * HD + d] = outv;
}

// ---------------------------------------------------------------------------
// Causal flash attention, fp32, online softmax, GQA group=4.
// 64x64 tiles, D=128, 256 threads (16x16 thread grid).
// Thread (ty,tx): scores 4x4 (rows ty*4.., cols tx*4..), output 4 rows x 8 cols.
// ---------------------------------------------------------------------------
#define BQ 64
#define BKV 64
#define QS 132   // padded row stride for Q/K/V tiles
#define PS 68    // padded row stride for P tile
#define FLASH_SMEM ((3*BQ*QS + BQ*PS)*4)   // 118784 bytes

__global__ void __launch_bounds__(256) flash_kernel(
    const float* __restrict__ gq, const float* __restrict__ gk,
    const float* __restrict__ gv, float* __restrict__ outb)
{
    extern __shared__ float sm[];
    float* sQ = sm;
    float* sK = sm + BQ * QS;
    float* sV = sK + BKV * QS;
    float* sP = sV + BKV * QS;

    const int qt = blockIdx.x;   // q tile 0..31
    const int h  = blockIdx.y;   // head 0..31
    const int b  = blockIdx.z;   // batch
    const int kvh = h >> 2;
    const int tid = threadIdx.x;
    const int ty = tid >> 4;
    const int tx = tid & 15;

    const float* Q = gq + ((size_t)(b * NH + h) * SEQ + (size_t)qt * BQ) * HD;
    const float* K = gk + (size_t)(b * NKV + kvh) * SEQ * HD;
    const float* V = gv + (size_t)(b * NKV + kvh) * SEQ * HD;

    // load Q tile
    for (int f = tid; f < BQ * (HD / 4); f += 256) {
        const int r = f >> 5, c = (f & 31) << 2;
        *(float4*)&sQ[r * QS + c] = *(const float4*)&Q[(size_t)r * HD + c];
    }

    float acc[4][8];
#pragma unroll
    for (int i = 0; i < 4; i++)
#pragma unroll
        for (int j = 0; j < 8; j++) acc[i][j] = 0.f;
    float mrow[4], lrow[4];
#pragma unroll
    for (int i = 0; i < 4; i++) { mrow[i] = -INFINITY; lrow[i] = 0.f; }

    const float scale = 0.08838834764831843f;   // 128^-0.5

    for (int jt = 0; jt <= qt; jt++) {
        const float* Kt = K + (size_t)jt * BKV * HD;
        const float* Vt = V + (size_t)jt * BKV * HD;
        __syncthreads();   // previous tile fully consumed (and Q visible on first iter)
        for (int f = tid; f < BKV * (HD / 4); f += 256) {
            const int r = f >> 5, c = (f & 31) << 2;
            *(float4*)&sK[r * QS + c] = *(const float4*)&Kt[(size_t)r * HD + c];
            *(float4*)&sV[r * QS + c] = *(const float4*)&Vt[(size_t)r * HD + c];
        }
        __syncthreads();

        // scores 4x4
        float sc[4][4];
#pragma unroll
        for (int i = 0; i < 4; i++)
#pragma unroll
            for (int j = 0; j < 4; j++) sc[i][j] = 0.f;

#pragma unroll 4
        for (int d = 0; d < HD; d += 4) {
            float4 qv[4], kv[4];
#pragma unroll
            for (int i = 0; i < 4; i++) qv[i] = *(const float4*)&sQ[(ty * 4 + i) * QS + d];
#pragma unroll
            for (int j = 0; j < 4; j++) kv[j] = *(const float4*)&sK[(tx * 4 + j) * QS + d];
#pragma unroll
            for (int i = 0; i < 4; i++)
#pragma unroll
                for (int j = 0; j < 4; j++)
                    sc[i][j] += qv[i].x * kv[j].x + qv[i].y * kv[j].y
                              + qv[i].z * kv[j].z + qv[i].w * kv[j].w;
        }

        const bool diag = (jt == qt);
#pragma unroll
        for (int i = 0; i < 4; i++) {
            const int qi = ty * 4 + i;
#pragma unroll
            for (int j = 0; j < 4; j++) {
                float s = sc[i][j] * scale;
                if (diag && (tx * 4 + j) > qi) s = -INFINITY;
                sc[i][j] = s;
            }
        }

        // online softmax (row groups span 16 lanes with same ty within a warp)
#pragma unroll
        for (int i = 0; i < 4; i++) {
            float rm = fmaxf(fmaxf(sc[i][0], sc[i][1]), fmaxf(sc[i][2], sc[i][3]));
            rm = fmaxf(rm, __shfl_xor_sync(0xffffffffu, rm, 1));
            rm = fmaxf(rm, __shfl_xor_sync(0xffffffffu, rm, 2));
            rm = fmaxf(rm, __shfl_xor_sync(0xffffffffu, rm, 4));
            rm = fmaxf(rm, __shfl_xor_sync(0xffffffffu, rm, 8));
            const float mn = fmaxf(mrow[i], rm);
            const float corr = __expf(mrow[i] - mn);
            mrow[i] = mn;
            float ps = 0.f;
#pragma unroll
            for (int j = 0; j < 4; j++) {
                const float p = __expf(sc[i][j] - mn);
                sP[(ty * 4 + i) * PS + tx * 4 + j] = p;
                ps += p;
            }
            ps += __shfl_xor_sync(0xffffffffu, ps, 1);
            ps += __shfl_xor_sync(0xffffffffu, ps, 2);
            ps += __shfl_xor_sync(0xffffffffu, ps, 4);
            ps += __shfl_xor_sync(0xffffffffu, ps, 8);
            lrow[i] = lrow[i] * corr + ps;
#pragma unroll
            for (int j = 0; j < 8; j++) acc[i][j] *= corr;
        }

        __syncthreads();   // sP complete

        // P @ V : each thread accumulates its 4 rows x 8 output cols
#pragma unroll 8
        for (int j = 0; j < BKV; j++) {
            float pv[4];
#pragma unroll
            for (int i = 0; i < 4; i++) pv[i] = sP[(ty * 4 + i) * PS + j];
            const float4 v0 = *(const float4*)&sV[j * QS + tx * 8];
            const float4 v1 = *(const float4*)&sV[j * QS + tx * 8 + 4];
#pragma unroll
            for (int i = 0; i < 4; i++) {
                acc[i][0] += pv[i] * v0.x; acc[i][1] += pv[i] * v0.y;
                acc[i][2] += pv[i] * v0.z; acc[i][3] += pv[i] * v0.w;
                acc[i][4] += pv[i] * v1.x; acc[i][5] += pv[i] * v1.y;
                acc[i][6] += pv[i] * v1.z; acc[i][7] += pv[i] * v1.w;
            }
        }
    }

    // epilogue: normalize and write [B,S,NH*HD]
    float* outp = outb + ((size_t)b * SEQ + (size_t)qt * BQ) * HID + (size_t)h * HD;
#pragma unroll
    for (int i = 0; i < 4; i++) {
        const float il = 1.f / lrow[i];
        float* op = outp + (size_t)(ty * 4 + i) * HID + tx * 8;
        float4 o0 = make_float4(acc[i][0] * il, acc[i][1] * il, acc[i][2] * il, acc[i][3] * il);
        float4 o1 = make_float4(acc[i][4] * il, acc[i][5] * il, acc[i][6] * il, acc[i][7] * il);
        *(float4*)op = o0;
        *(float4*)(op + 4) = o1;
    }
}

// ---------------------------------------------------------------------------
extern "C" void kernel_launch(void* const* d_in, const int* in_sizes, int n_in,
                              void* d_out, int out_size)
{
    const float* hidden    = (const float*)d_in[0];
    const int*   positions = (const int*)d_in[1];
    const float* wqkv      = (const float*)d_in[2];
    const float* qnw       = (const float*)d_in[3];
    const float* knw       = (const float*)d_in[4];
    const float* wo        = (const float*)d_in[5];
    float* out = (float*)d_out;

    float *qkv, *q, *k, *v, *attn;
    cudaGetSymbolAddress((void**)&qkv, g_qkv);
    cudaGetSymbolAddress((void**)&q, g_q);
    cudaGetSymbolAddress((void**)&k, g_k);
    cudaGetSymbolAddress((void**)&v, g_v);
    cudaGetSymbolAddress((void**)&attn, g_attn);

    cudaFuncSetAttribute(flash_kernel,
                         cudaFuncAttributeMaxDynamicSharedMemorySize, FLASH_SMEM);

    // 1) QKV projection: [4096,4096] @ [6144,4096]^T
    dim3 g1(QKVO / BN, MTOK / BM);
    gemm_nt_kernel<<<g1, 256>>>(hidden, wqkv, qkv, MTOK, QKVO, HID);

    // 2) RMSNorm + RoPE + scatter to head-major layout
    dim3 g2(MTOK, NH + 2 * NKV);
    norm_rope_kernel<<<g2, 128>>>(qkv, positions, qnw, knw, q, k, v);

    // 3) Causal GQA flash attention
    dim3 g3(SEQ / BQ, NH, NB);
    flash_kernel<<<g3, 256, FLASH_SMEM>>>(q, k, v, attn);

    // 4) Output projection: [4096,4096] @ [4096,4096]^T
    dim3 g4(HID / BN, MTOK / BM);
    gemm_nt_kernel<<<g4, 256>>>(attn, wo, out, MTOK, HID, HID);
}

// round 4
// speedup vs baseline: 1.5665x; 1.5665x over previous
#include <cuda_runtime.h>
#include <cuda_bf16.h>
#include <math.h>
#include <stdint.h>

// Problem constants
#define NB   2
#define SEQ  2048
#define HID  4096
#define NH   32
#define NKV  8
#define HD   128
#define QKVO ((NH + 2*NKV)*HD)   // 6144
#define MTOK (NB*SEQ)            // 4096

// Scratch (no cudaMalloc allowed)
__device__ float g_qkv[(size_t)MTOK * QKVO];
__device__ float g_q[(size_t)NB * NH * SEQ * HD];
__device__ float g_k[(size_t)NB * NKV * SEQ * HD];
__device__ float g_v[(size_t)NB * NKV * SEQ * HD];
__device__ float g_attn[(size_t)MTOK * HID];
// bf16 split scratch
__device__ __nv_bfloat16 g_ahi[(size_t)MTOK * HID];
__device__ __nv_bfloat16 g_alo[(size_t)MTOK * HID];
__device__ __nv_bfloat16 g_whi[(size_t)QKVO * HID];
__device__ __nv_bfloat16 g_wlo[(size_t)QKVO * HID];

// ===========================================================================
// Low-level helpers (sm_80-baseline ISA only: ldmatrix / mma.sync / cp.async)
// ===========================================================================
__device__ __forceinline__ uint32_t smem_to_u32(const void* p) {
    uint32_t a;
    asm("{ .reg .u64 t; cvta.to.shared.u64 t, %1; cvt.u32.u64 %0, t; }" : "=r"(a) : "l"(p));
    return a;
}
__device__ __forceinline__ void ldsm_x4(uint32_t& r0, uint32_t& r1, uint32_t& r2,
                                        uint32_t& r3, uint32_t addr) {
    asm volatile("ldmatrix.sync.aligned.m8n8.x4.shared.b16 {%0,%1,%2,%3}, [%4];"
                 : "=r"(r0), "=r"(r1), "=r"(r2), "=r"(r3) : "r"(addr));
}
__device__ __forceinline__ void mma_bf16(float* c, uint32_t a0, uint32_t a1,
                                         uint32_t a2, uint32_t a3,
                                         uint32_t b0, uint32_t b1) {
    asm volatile(
        "mma.sync.aligned.m16n8k16.row.col.f32.bf16.bf16.f32 "
        "{%0,%1,%2,%3}, {%4,%5,%6,%7}, {%8,%9}, {%0,%1,%2,%3};"
        : "+f"(c[0]), "+f"(c[1]), "+f"(c[2]), "+f"(c[3])
        : "r"(a0), "r"(a1), "r"(a2), "r"(a3), "r"(b0), "r"(b1));
}
__device__ __forceinline__ void cpa16(uint32_t dst, const void* src) {
    asm volatile("cp.async.cg.shared.global [%0], [%1], 16;" :: "r"(dst), "l"(src));
}
#define CP_COMMIT() asm volatile("cp.async.commit_group;" ::: "memory")
#define CP_WAIT0()  asm volatile("cp.async.wait_group 0;" ::: "memory")

// ===========================================================================
// Split conversion: fp32 -> (bf16 hi, bf16 lo)
// ===========================================================================
__global__ void __launch_bounds__(256) conv_split_kernel(
    const float* __restrict__ x, __nv_bfloat16* __restrict__ hi,
    __nv_bfloat16* __restrict__ lo, size_t n)
{
    size_t i = ((size_t)blockIdx.x * 256 + threadIdx.x) * 4;
    if (i >= n) return;
    float4 v = *(const float4*)(x + i);
    float f[4] = {v.x, v.y, v.z, v.w};
    __nv_bfloat16 h[4], l[4];
#pragma unroll
    for (int j = 0; j < 4; j++) {
        h[j] = __float2bfloat16(f[j]);
        l[j] = __float2bfloat16(f[j] - __bfloat162float(h[j]));
    }
    *(uint2*)(hi + i) = *(uint2*)h;
    *(uint2*)(lo + i) = *(uint2*)l;
}

// ===========================================================================
// bf16x3 GEMM-NT via mma.sync: C[M,N] = A[M,K] * W[N,K]^T (fp32-accurate)
// CTA 128x128, K-chunk 32, 256 threads (8 warps, 2x4), double-buffered cp.async.
// smem tile stride = 40 bf16 (80B) -> conflict-free ldmatrix.
// ===========================================================================
#define GK 32
#define TSTR 40                       // padded row stride (bf16 elems)
#define TILE_PB (128 * TSTR * 2)      // 10240 B per 128x32 tile
#define STAGE_B (4 * TILE_PB)         // Ahi, Alo, Bhi, Blo = 40960 B
#define GEMM_SMEM (2 * STAGE_B)       // 81920 B

__global__ void __launch_bounds__(256) gemm_bf16x3_kernel(
    const __nv_bfloat16* __restrict__ Ah, const __nv_bfloat16* __restrict__ Al,
    const __nv_bfloat16* __restrict__ Bh, const __nv_bfloat16* __restrict__ Bl,
    float* __restrict__ C, int M, int N, int K)
{
    extern __shared__ char smem[];
    const uint32_t sb = smem_to_u32(smem);
    const int tid  = threadIdx.x;
    const int wid  = tid >> 5;
    const int lane = tid & 31;
    const int warp_m = wid >> 2;        // 0..1  (64 rows each)
    const int warp_n = wid & 3;         // 0..3  (32 cols each)
    const int bm = blockIdx.y * 128;
    const int bn = blockIdx.x * 128;

    const __nv_bfloat16* srcs[4] = {
        Ah + (size_t)bm * K, Al + (size_t)bm * K,
        Bh + (size_t)bn * K, Bl + (size_t)bn * K };

    float acc[4][4][4];                 // [m-tile][n-tile][reg]
#pragma unroll
    for (int i = 0; i < 4; i++)
#pragma unroll
        for (int j = 0; j < 4; j++)
#pragma unroll
            for (int r = 0; r < 4; r++) acc[i][j][r] = 0.f;

    // prefetch one 128x32 chunk (4 tiles) into stage s
    auto prefetch = [&](int k0, int s) {
        const uint32_t base = sb + s * STAGE_B;
#pragma unroll
        for (int t = 0; t < 4; t++) {
            const __nv_bfloat16* src = srcs[t];
#pragma unroll
            for (int i = 0; i < 2; i++) {
                const int f = tid + i * 256;        // 0..511
                const int r = f >> 2, sg = f & 3;   // row, 16B segment
                cpa16(base + t * TILE_PB + (uint32_t)(r * TSTR + sg * 8) * 2,
                      src + (size_t)r * K + k0 + sg * 8);
            }
        }
        CP_COMMIT();
    };

    const int NC = K / GK;
    prefetch(0, 0);

    // ldmatrix address components (constant across chunks)
    const int a_r = lane & 15;              // row within 16
    const int a_c = (lane >> 4) * 8;        // k offset 0/8
    const int b_g = lane >> 3;              // 0..3
    const int b_r = lane & 7;
    const int b_jj = b_g >> 1;              // n-subtile within pair
    const int b_kk = (b_g & 1) * 8;         // k offset 0/8

    for (int c = 0; c < NC; c++) {
        CP_WAIT0();
        __syncthreads();
        if (c + 1 < NC) prefetch((c + 1) * GK, (c + 1) & 1);

        const uint32_t base = sb + (c & 1) * STAGE_B;
#pragma unroll
        for (int ks = 0; ks < 2; ks++) {
            const int kb = ks * 16;
            // A fragments (hi & lo), 4 m-tiles
            uint32_t ah[4][4], al[4][4];
#pragma unroll
            for (int mt = 0; mt < 4; mt++) {
                const uint32_t off =
                    (uint32_t)((warp_m * 64 + mt * 16 + a_r) * TSTR + kb + a_c) * 2;
                ldsm_x4(ah[mt][0], ah[mt][1], ah[mt][2], ah[mt][3], base + off);
                ldsm_x4(al[mt][0], al[mt][1], al[mt][2], al[mt][3],
                        base + TILE_PB + off);
            }
            // B fragments: 2 n-tile pairs
#pragma unroll
            for (int jp = 0; jp < 2; jp++) {
                const uint32_t boff =
                    (uint32_t)((warp_n * 32 + (jp * 2 + b_jj) * 8 + b_r) * TSTR
                               + kb + b_kk) * 2;
                uint32_t bh0, bh1, bh2, bh3, bl0, bl1, bl2, bl3;
                ldsm_x4(bh0, bh1, bh2, bh3, base + 2 * TILE_PB + boff);
                ldsm_x4(bl0, bl1, bl2, bl3, base + 3 * TILE_PB + boff);
#pragma unroll
                for (int mt = 0; mt < 4; mt++) {
                    float* c0 = acc[mt][jp * 2];
                    float* c1 = acc[mt][jp * 2 + 1];
                    mma_bf16(c0, ah[mt][0], ah[mt][1], ah[mt][2], ah[mt][3], bh0, bh1);
                    mma_bf16(c1, ah[mt][0], ah[mt][1], ah[mt][2], ah[mt][3], bh2, bh3);
                    mma_bf16(c0, ah[mt][0], ah[mt][1], ah[mt][2], ah[mt][3], bl0, bl1);
                    mma_bf16(c1, ah[mt][0], ah[mt][1], ah[mt][2], ah[mt][3], bl2, bl3);
                    mma_bf16(c0, al[mt][0], al[mt][1], al[mt][2], al[mt][3], bh0, bh1);
                    mma_bf16(c1, al[mt][0], al[mt][1], al[mt][2], al[mt][3], bh2, bh3);
                }
            }
        }
        __syncthreads();
    }

    // epilogue: direct stores (thread holds (row, col*2) float2 pairs)
#pragma unroll
    for (int mt = 0; mt < 4; mt++) {
        const int row = bm + warp_m * 64 + mt * 16 + (lane >> 2);
#pragma unroll
        for (int nt = 0; nt < 4; nt++) {
            const int col = bn + warp_n * 32 + nt * 8 + (lane & 3) * 2;
            float* cp0 = C + (size_t)row * N + col;
            float* cp1 = C + (size_t)(row + 8) * N + col;
            *(float2*)cp0 = make_float2(acc[mt][nt][0], acc[mt][nt][1]);
            *(float2*)cp1 = make_float2(acc[mt][nt][2], acc[mt][nt][3]);
        }
    }
}

// ---------------------------------------------------------------------------
// Per-head RMSNorm + RoPE, scatter to head-major q/k/v buffers.
// ---------------------------------------------------------------------------
__global__ void __launch_bounds__(128) norm_rope_kernel(
    const float* __restrict__ qkv, const int* __restrict__ positions,
    const float* __restrict__ qw, const float* __restrict__ kw,
    float* __restrict__ gq, float* __restrict__ gk, float* __restrict__ gv)
{
    const int token = blockIdx.x;
    const int b = token / SEQ;
    const int s = token - b * SEQ;
    const int head = blockIdx.y;
    const int d = threadIdx.x;

    if (head >= NH + NKV) {
        const int kvh = head - NH - NKV;
        float x = qkv[(size_t)token * QKVO + (size_t)(NH + NKV) * HD + kvh * HD + d];
        gv[((size_t)(b * NKV + kvh) * SEQ + s) * HD + d] = x;
        return;
    }

    const bool is_q = head < NH;
    const float* src = qkv + (size_t)token * QKVO
                     + (is_q ? (size_t)head * HD : (size_t)NH * HD + (size_t)(head - NH) * HD);
    float x = src[d];

    __shared__ float red[4];
    __shared__ float ys[HD];

    float sq = x * x;
#pragma unroll
    for (int o = 16; o > 0; o >>= 1) sq += __shfl_xor_sync(0xffffffffu, sq, o);
    if ((d & 31) == 0) red[d >> 5] = sq;
    __syncthreads();
    const float var = (red[0] + red[1] + red[2] + red[3]) * (1.0f / HD);
    const float rn = rsqrtf(var + 1e-6f);
    const float w = is_q ? qw[d] : kw[d];
    ys[d] = x * rn * w;
    __syncthreads();

    const int pos = positions[s];
    const int i = d & 63;
    const double inv = exp(-(double)i * (9.210340371976184 / 64.0));
    const double ang = (double)pos * inv;
    double sd, cd;
    sincos(ang, &sd, &cd);
    const float c = (float)cd, sn = (float)sd;

    const float x1 = ys[i];
    const float x2 = ys[i + 64];
    const float outv = (d < 64) ? (x1 * c - x2 * sn) : (x2 * c + x1 * sn);

    if (is_q)
        gq[((size_t)(b * NH + head) * SEQ + s) * HD + d] = outv;
    else
        gk[((size_t)(b * NKV + (head - NH)) * SEQ + s) * HD + d] = outv;
}

// ---------------------------------------------------------------------------
// Causal flash attention, fp32, online softmax, GQA group=4. (unchanged)
// ---------------------------------------------------------------------------
#define BQ 64
#define BKV 64
#define QS 132
#define PS 68
#define FLASH_SMEM ((3*BQ*QS + BQ*PS)*4)

__global__ void __launch_bounds__(256) flash_kernel(
    const float* __restrict__ gq, const float* __restrict__ gk,
    const float* __restrict__ gv, float* __restrict__ outb)
{
    extern __shared__ float sm[];
    float* sQ = sm;
    float* sK = sm + BQ * QS;
    float* sV = sK + BKV * QS;
    float* sP = sV + BKV * QS;

    const int qt = blockIdx.x;
    const int h  = blockIdx.y;
    const int b  = blockIdx.z;
    const int kvh = h >> 2;
    const int tid = threadIdx.x;
    const int ty = tid >> 4;
    const int tx = tid & 15;

    const float* Q = gq + ((size_t)(b * NH + h) * SEQ + (size_t)qt * BQ) * HD;
    const float* K = gk + (size_t)(b * NKV + kvh) * SEQ * HD;
    const float* V = gv + (size_t)(b * NKV + kvh) * SEQ * HD;

    for (int f = tid; f < BQ * (HD / 4); f += 256) {
        const int r = f >> 5, c = (f & 31) << 2;
        *(float4*)&sQ[r * QS + c] = *(const float4*)&Q[(size_t)r * HD + c];
    }

    float acc[4][8];
#pragma unroll
    for (int i = 0; i < 4; i++)
#pragma unroll
        for (int j = 0; j < 8; j++) acc[i][j] = 0.f;
    float mrow[4], lrow[4];
#pragma unroll
    for (int i = 0; i < 4; i++) { mrow[i] = -INFINITY; lrow[i] = 0.f; }

    const float scale = 0.08838834764831843f;

    for (int jt = 0; jt <= qt; jt++) {
        const float* Kt = K + (size_t)jt * BKV * HD;
        const float* Vt = V + (size_t)jt * BKV * HD;
        __syncthreads();
        for (int f = tid; f < BKV * (HD / 4); f += 256) {
            const int r = f >> 5, c = (f & 31) << 2;
            *(float4*)&sK[r * QS + c] = *(const float4*)&Kt[(size_t)r * HD + c];
            *(float4*)&sV[r * QS + c] = *(const float4*)&Vt[(size_t)r * HD + c];
        }
        __syncthreads();

        float sc[4][4];
#pragma unroll
        for (int i = 0; i < 4; i++)
#pragma unroll
            for (int j = 0; j < 4; j++) sc[i][j] = 0.f;

#pragma unroll 4
        for (int d = 0; d < HD; d += 4) {
            float4 qv[4], kv[4];
#pragma unroll
            for (int i = 0; i < 4; i++) qv[i] = *(const float4*)&sQ[(ty * 4 + i) * QS + d];
#pragma unroll
            for (int j = 0; j < 4; j++) kv[j] = *(const float4*)&sK[(tx * 4 + j) * QS + d];
#pragma unroll
            for (int i = 0; i < 4; i++)
#pragma unroll
                for (int j = 0; j < 4; j++)
                    sc[i][j] += qv[i].x * kv[j].x + qv[i].y * kv[j].y
                              + qv[i].z * kv[j].z + qv[i].w * kv[j].w;
        }

        const bool diag = (jt == qt);
#pragma unroll
        for (int i = 0; i < 4; i++) {
            const int qi = ty * 4 + i;
#pragma unroll
            for (int j = 0; j < 4; j++) {
                float s = sc[i][j] * scale;
                if (diag && (tx * 4 + j) > qi) s = -INFINITY;
                sc[i][j] = s;
            }
        }

#pragma unroll
        for (int i = 0; i < 4; i++) {
            float rm = fmaxf(fmaxf(sc[i][0], sc[i][1]), fmaxf(sc[i][2], sc[i][3]));
            rm = fmaxf(rm, __shfl_xor_sync(0xffffffffu, rm, 1));
            rm = fmaxf(rm, __shfl_xor_sync(0xffffffffu, rm, 2));
            rm = fmaxf(rm, __shfl_xor_sync(0xffffffffu, rm, 4));
            rm = fmaxf(rm, __shfl_xor_sync(0xffffffffu, rm, 8));
            const float mn = fmaxf(mrow[i], rm);
            const float corr = __expf(mrow[i] - mn);
            mrow[i] = mn;
            float ps = 0.f;
#pragma unroll
            for (int j = 0; j < 4; j++) {
                const float p = __expf(sc[i][j] - mn);
                sP[(ty * 4 + i) * PS + tx * 4 + j] = p;
                ps += p;
            }
            ps += __shfl_xor_sync(0xffffffffu, ps, 1);
            ps += __shfl_xor_sync(0xffffffffu, ps, 2);
            ps += __shfl_xor_sync(0xffffffffu, ps, 4);
            ps += __shfl_xor_sync(0xffffffffu, ps, 8);
            lrow[i] = lrow[i] * corr + ps;
#pragma unroll
            for (int j = 0; j < 8; j++) acc[i][j] *= corr;
        }

        __syncthreads();

#pragma unroll 8
        for (int j = 0; j < BKV; j++) {
            float pv[4];
#pragma unroll
            for (int i = 0; i < 4; i++) pv[i] = sP[(ty * 4 + i) * PS + j];
            const float4 v0 = *(const float4*)&sV[j * QS + tx * 8];
            const float4 v1 = *(const float4*)&sV[j * QS + tx * 8 + 4];
#pragma unroll
            for (int i = 0; i < 4; i++) {
                acc[i][0] += pv[i] * v0.x; acc[i][1] += pv[i] * v0.y;
                acc[i][2] += pv[i] * v0.z; acc[i][3] += pv[i] * v0.w;
                acc[i][4] += pv[i] * v1.x; acc[i][5] += pv[i] * v1.y;
                acc[i][6] += pv[i] * v1.z; acc[i][7] += pv[i] * v1.w;
            }
        }
    }

    float* outp = outb + ((size_t)b * SEQ + (size_t)qt * BQ) * HID + (size_t)h * HD;
#pragma unroll
    for (int i = 0; i < 4; i++) {
        const float il = 1.f / lrow[i];
        float* op = outp + (size_t)(ty * 4 + i) * HID + tx * 8;
        float4 o0 = make_float4(acc[i][0] * il, acc[i][1] * il, acc[i][2] * il, acc[i][3] * il);
        float4 o1 = make_float4(acc[i][4] * il, acc[i][5] * il, acc[i][6] * il, acc[i][7] * il);
        *(float4*)op = o0;
        *(float4*)(op + 4) = o1;
    }
}

// ---------------------------------------------------------------------------
extern "C" void kernel_launch(void* const* d_in, const int* in_sizes, int n_in,
                              void* d_out, int out_size)
{
    const float* hidden    = (const float*)d_in[0];
    const int*   positions = (const int*)d_in[1];
    const float* wqkv      = (const float*)d_in[2];
    const float* qnw       = (const float*)d_in[3];
    const float* knw       = (const float*)d_in[4];
    const float* wo        = (const float*)d_in[5];
    float* out = (float*)d_out;

    float *qkv, *q, *k, *v, *attn;
    __nv_bfloat16 *ahi, *alo, *whi, *wlo;
    cudaGetSymbolAddress((void**)&qkv, g_qkv);
    cudaGetSymbolAddress((void**)&q, g_q);
    cudaGetSymbolAddress((void**)&k, g_k);
    cudaGetSymbolAddress((void**)&v, g_v);
    cudaGetSymbolAddress((void**)&attn, g_attn);
    cudaGetSymbolAddress((void**)&ahi, g_ahi);
    cudaGetSymbolAddress((void**)&alo, g_alo);
    cudaGetSymbolAddress((void**)&whi, g_whi);
    cudaGetSymbolAddress((void**)&wlo, g_wlo);

    cudaFuncSetAttribute(flash_kernel,
                         cudaFuncAttributeMaxDynamicSharedMemorySize, FLASH_SMEM);
    cudaFuncSetAttribute(gemm_bf16x3_kernel,
                         cudaFuncAttributeMaxDynamicSharedMemorySize, GEMM_SMEM);

    const size_t nA  = (size_t)MTOK * HID;
    const size_t nW1 = (size_t)QKVO * HID;

    // 1) split-convert hidden and wqkv
    conv_split_kernel<<<(unsigned)((nA / 4 + 255) / 256), 256>>>(hidden, ahi, alo, nA);
    conv_split_kernel<<<(unsigned)((nW1 / 4 + 255) / 256), 256>>>(wqkv, whi, wlo, nW1);

    // 2) QKV projection (bf16x3 mma.sync): [4096,4096] @ [6144,4096]^T
    dim3 g1(QKVO / 128, MTOK / 128);
    gemm_bf16x3_kernel<<<g1, 256, GEMM_SMEM>>>(ahi, alo, whi, wlo, qkv, MTOK, QKVO, HID);

    // 3) RMSNorm + RoPE + scatter
    dim3 g2(MTOK, NH + 2 * NKV);
    norm_rope_kernel<<<g2, 128>>>(qkv, positions, qnw, knw, q, k, v);

    // 4) Causal GQA flash attention
    dim3 g3(SEQ / BQ, NH, NB);
    flash_kernel<<<g3, 256, FLASH_SMEM>>>(q, k, v, attn);

    // 5) split-convert attn and wo, then output projection
    conv_split_kernel<<<(unsigned)((nA / 4 + 255) / 256), 256>>>(attn, ahi, alo, nA);
    conv_split_kernel<<<(unsigned)((nA / 4 + 255) / 256), 256>>>(wo, whi, wlo, nA);
    dim3 g4(HID / 128, MTOK / 128);
    gemm_bf16x3_kernel<<<g4, 256, GEMM_SMEM>>>(ahi, alo, whi, wlo, out, MTOK, HID, HID);
}

// round 5
// speedup vs baseline: 2.5078x; 1.6009x over previous
#include <cuda_runtime.h>
#include <cuda_bf16.h>
#include <math.h>
#include <stdint.h>

// Problem constants
#define NB   2
#define SEQ  2048
#define HID  4096
#define NH   32
#define NKV  8
#define HD   128
#define QKVO ((NH + 2*NKV)*HD)   // 6144
#define MTOK (NB*SEQ)            // 4096

// Scratch (no cudaMalloc allowed)
__device__ float g_qkv[(size_t)MTOK * QKVO];
__device__ __nv_bfloat16 g_ahi[(size_t)MTOK * HID];
__device__ __nv_bfloat16 g_alo[(size_t)MTOK * HID];
__device__ __nv_bfloat16 g_whi[(size_t)QKVO * HID];
__device__ __nv_bfloat16 g_wlo[(size_t)QKVO * HID];
// head-major split q/k/v (bf16 hi/lo)
__device__ __nv_bfloat16 g_qh[(size_t)NB * NH * SEQ * HD];
__device__ __nv_bfloat16 g_ql[(size_t)NB * NH * SEQ * HD];
__device__ __nv_bfloat16 g_kh[(size_t)NB * NKV * SEQ * HD];
__device__ __nv_bfloat16 g_kl[(size_t)NB * NKV * SEQ * HD];
__device__ __nv_bfloat16 g_vh[(size_t)NB * NKV * SEQ * HD];
__device__ __nv_bfloat16 g_vl[(size_t)NB * NKV * SEQ * HD];

// ===========================================================================
// Low-level helpers (sm_80-baseline ISA: ldmatrix / mma.sync / cp.async)
// ===========================================================================
__device__ __forceinline__ uint32_t smem_to_u32(const void* p) {
    uint32_t a;
    asm("{ .reg .u64 t; cvta.to.shared.u64 t, %1; cvt.u32.u64 %0, t; }" : "=r"(a) : "l"(p));
    return a;
}
__device__ __forceinline__ void ldsm_x4(uint32_t& r0, uint32_t& r1, uint32_t& r2,
                                        uint32_t& r3, uint32_t addr) {
    asm volatile("ldmatrix.sync.aligned.m8n8.x4.shared.b16 {%0,%1,%2,%3}, [%4];"
                 : "=r"(r0), "=r"(r1), "=r"(r2), "=r"(r3) : "r"(addr));
}
__device__ __forceinline__ void ldsm_x4_t(uint32_t& r0, uint32_t& r1, uint32_t& r2,
                                          uint32_t& r3, uint32_t addr) {
    asm volatile("ldmatrix.sync.aligned.m8n8.x4.trans.shared.b16 {%0,%1,%2,%3}, [%4];"
                 : "=r"(r0), "=r"(r1), "=r"(r2), "=r"(r3) : "r"(addr));
}
__device__ __forceinline__ void mma_bf16(float* c, uint32_t a0, uint32_t a1,
                                         uint32_t a2, uint32_t a3,
                                         uint32_t b0, uint32_t b1) {
    asm volatile(
        "mma.sync.aligned.m16n8k16.row.col.f32.bf16.bf16.f32 "
        "{%0,%1,%2,%3}, {%4,%5,%6,%7}, {%8,%9}, {%0,%1,%2,%3};"
        : "+f"(c[0]), "+f"(c[1]), "+f"(c[2]), "+f"(c[3])
        : "r"(a0), "r"(a1), "r"(a2), "r"(a3), "r"(b0), "r"(b1));
}
__device__ __forceinline__ void cpa16(uint32_t dst, const void* src) {
    asm volatile("cp.async.cg.shared.global [%0], [%1], 16;" :: "r"(dst), "l"(src));
}
#define CP_COMMIT() asm volatile("cp.async.commit_group;" ::: "memory")
#define CP_WAIT0()  asm volatile("cp.async.wait_group 0;" ::: "memory")

__device__ __forceinline__ uint32_t pack2_bf16(float a, float b) {
    __nv_bfloat162 t = __floats2bfloat162_rn(a, b);
    return *reinterpret_cast<uint32_t*>(&t);
}

// ===========================================================================
// Split conversion: fp32 -> (bf16 hi, bf16 lo)
// ===========================================================================
__global__ void __launch_bounds__(256) conv_split_kernel(
    const float* __restrict__ x, __nv_bfloat16* __restrict__ hi,
    __nv_bfloat16* __restrict__ lo, size_t n)
{
    size_t i = ((size_t)blockIdx.x * 256 + threadIdx.x) * 4;
    if (i >= n) return;
    float4 v = *(const float4*)(x + i);
    float f[4] = {v.x, v.y, v.z, v.w};
    __nv_bfloat16 h[4], l[4];
#pragma unroll
    for (int j = 0; j < 4; j++) {
        h[j] = __float2bfloat16(f[j]);
        l[j] = __float2bfloat16(f[j] - __bfloat162float(h[j]));
    }
    *(uint2*)(hi + i) = *(uint2*)h;
    *(uint2*)(lo + i) = *(uint2*)l;
}

// ===========================================================================
// bf16x3 GEMM-NT via mma.sync (unchanged from R4 — verified)
// ===========================================================================
#define GK 32
#define TSTR 40
#define TILE_PB (128 * TSTR * 2)
#define STAGE_B (4 * TILE_PB)
#define GEMM_SMEM (2 * STAGE_B)

__global__ void __launch_bounds__(256) gemm_bf16x3_kernel(
    const __nv_bfloat16* __restrict__ Ah, const __nv_bfloat16* __restrict__ Al,
    const __nv_bfloat16* __restrict__ Bh, const __nv_bfloat16* __restrict__ Bl,
    float* __restrict__ C, int M, int N, int K)
{
    extern __shared__ char smem[];
    const uint32_t sb = smem_to_u32(smem);
    const int tid  = threadIdx.x;
    const int wid  = tid >> 5;
    const int lane = tid & 31;
    const int warp_m = wid >> 2;
    const int warp_n = wid & 3;
    const int bm = blockIdx.y * 128;
    const int bn = blockIdx.x * 128;

    const __nv_bfloat16* srcs[4] = {
        Ah + (size_t)bm * K, Al + (size_t)bm * K,
        Bh + (size_t)bn * K, Bl + (size_t)bn * K };

    float acc[4][4][4];
#pragma unroll
    for (int i = 0; i < 4; i++)
#pragma unroll
        for (int j = 0; j < 4; j++)
#pragma unroll
            for (int r = 0; r < 4; r++) acc[i][j][r] = 0.f;

    auto prefetch = [&](int k0, int s) {
        const uint32_t base = sb + s * STAGE_B;
#pragma unroll
        for (int t = 0; t < 4; t++) {
            const __nv_bfloat16* src = srcs[t];
#pragma unroll
            for (int i = 0; i < 2; i++) {
                const int f = tid + i * 256;
                const int r = f >> 2, sg = f & 3;
                cpa16(base + t * TILE_PB + (uint32_t)(r * TSTR + sg * 8) * 2,
                      src + (size_t)r * K + k0 + sg * 8);
            }
        }
        CP_COMMIT();
    };

    const int NC = K / GK;
    prefetch(0, 0);

    const int a_r = lane & 15;
    const int a_c = (lane >> 4) * 8;
    const int b_g = lane >> 3;
    const int b_r = lane & 7;
    const int b_jj = b_g >> 1;
    const int b_kk = (b_g & 1) * 8;

    for (int c = 0; c < NC; c++) {
        CP_WAIT0();
        __syncthreads();
        if (c + 1 < NC) prefetch((c + 1) * GK, (c + 1) & 1);

        const uint32_t base = sb + (c & 1) * STAGE_B;
#pragma unroll
        for (int ks = 0; ks < 2; ks++) {
            const int kb = ks * 16;
            uint32_t ah[4][4], al[4][4];
#pragma unroll
            for (int mt = 0; mt < 4; mt++) {
                const uint32_t off =
                    (uint32_t)((warp_m * 64 + mt * 16 + a_r) * TSTR + kb + a_c) * 2;
                ldsm_x4(ah[mt][0], ah[mt][1], ah[mt][2], ah[mt][3], base + off);
                ldsm_x4(al[mt][0], al[mt][1], al[mt][2], al[mt][3],
                        base + TILE_PB + off);
            }
#pragma unroll
            for (int jp = 0; jp < 2; jp++) {
                const uint32_t boff =
                    (uint32_t)((warp_n * 32 + (jp * 2 + b_jj) * 8 + b_r) * TSTR
                               + kb + b_kk) * 2;
                uint32_t bh0, bh1, bh2, bh3, bl0, bl1, bl2, bl3;
                ldsm_x4(bh0, bh1, bh2, bh3, base + 2 * TILE_PB + boff);
                ldsm_x4(bl0, bl1, bl2, bl3, base + 3 * TILE_PB + boff);
#pragma unroll
                for (int mt = 0; mt < 4; mt++) {
                    float* c0 = acc[mt][jp * 2];
                    float* c1 = acc[mt][jp * 2 + 1];
                    mma_bf16(c0, ah[mt][0], ah[mt][1], ah[mt][2], ah[mt][3], bh0, bh1);
                    mma_bf16(c1, ah[mt][0], ah[mt][1], ah[mt][2], ah[mt][3], bh2, bh3);
                    mma_bf16(c0, ah[mt][0], ah[mt][1], ah[mt][2], ah[mt][3], bl0, bl1);
                    mma_bf16(c1, ah[mt][0], ah[mt][1], ah[mt][2], ah[mt][3], bl2, bl3);
                    mma_bf16(c0, al[mt][0], al[mt][1], al[mt][2], al[mt][3], bh0, bh1);
                    mma_bf16(c1, al[mt][0], al[mt][1], al[mt][2], al[mt][3], bh2, bh3);
                }
            }
        }
        __syncthreads();
    }

#pragma unroll
    for (int mt = 0; mt < 4; mt++) {
        const int row = bm + warp_m * 64 + mt * 16 + (lane >> 2);
#pragma unroll
        for (int nt = 0; nt < 4; nt++) {
            const int col = bn + warp_n * 32 + nt * 8 + (lane & 3) * 2;
            float* cp0 = C + (size_t)row * N + col;
            float* cp1 = C + (size_t)(row + 8) * N + col;
            *(float2*)cp0 = make_float2(acc[mt][nt][0], acc[mt][nt][1]);
            *(float2*)cp1 = make_float2(acc[mt][nt][2], acc[mt][nt][3]);
        }
    }
}

// ---------------------------------------------------------------------------
// RMSNorm + RoPE -> pre-split bf16 hi/lo head-major q/k/v.
// Softmax scale (HD^-0.5) folded into Q.
// ---------------------------------------------------------------------------
__global__ void __launch_bounds__(128) norm_rope_split_kernel(
    const float* __restrict__ qkv, const int* __restrict__ positions,
    const float* __restrict__ qw, const float* __restrict__ kw,
    __nv_bfloat16* __restrict__ qh, __nv_bfloat16* __restrict__ ql,
    __nv_bfloat16* __restrict__ kh, __nv_bfloat16* __restrict__ kl,
    __nv_bfloat16* __restrict__ vh, __nv_bfloat16* __restrict__ vl)
{
    const int token = blockIdx.x;
    const int b = token / SEQ;
    const int s = token - b * SEQ;
    const int head = blockIdx.y;
    const int d = threadIdx.x;

    if (head >= NH + NKV) {      // V: plain split
        const int kvh = head - NH - NKV;
        float x = qkv[(size_t)token * QKVO + (size_t)(NH + NKV) * HD + kvh * HD + d];
        const size_t o = ((size_t)(b * NKV + kvh) * SEQ + s) * HD + d;
        __nv_bfloat16 h = __float2bfloat16(x);
        vh[o] = h;
        vl[o] = __float2bfloat16(x - __bfloat162float(h));
        return;
    }

    const bool is_q = head < NH;
    const float* src = qkv + (size_t)token * QKVO
                     + (is_q ? (size_t)head * HD : (size_t)NH * HD + (size_t)(head - NH) * HD);
    float x = src[d];

    __shared__ float red[4];
    __shared__ float ys[HD];

    float sq = x * x;
#pragma unroll
    for (int o = 16; o > 0; o >>= 1) sq += __shfl_xor_sync(0xffffffffu, sq, o);
    if ((d & 31) == 0) red[d >> 5] = sq;
    __syncthreads();
    const float var = (red[0] + red[1] + red[2] + red[3]) * (1.0f / HD);
    const float rn = rsqrtf(var + 1e-6f);
    const float w = is_q ? qw[d] : kw[d];
    ys[d] = x * rn * w;
    __syncthreads();

    const int pos = positions[s];
    const int i = d & 63;
    const double inv = exp(-(double)i * (9.210340371976184 / 64.0));
    const double ang = (double)pos * inv;
    double sd, cd;
    sincos(ang, &sd, &cd);
    const float c = (float)cd, sn = (float)sd;

    const float x1 = ys[i];
    const float x2 = ys[i + 64];
    float outv = (d < 64) ? (x1 * c - x2 * sn) : (x2 * c + x1 * sn);
    if (is_q) outv *= 0.08838834764831843f;

    __nv_bfloat16 h = __float2bfloat16(outv);
    __nv_bfloat16 l = __float2bfloat16(outv - __bfloat162float(h));

    if (is_q) {
        const size_t o = ((size_t)(b * NH + head) * SEQ + s) * HD + d;
        qh[o] = h; ql[o] = l;
    } else {
        const size_t o = ((size_t)(b * NKV + (head - NH)) * SEQ + s) * HD + d;
        kh[o] = h; kl[o] = l;
    }
}

// ---------------------------------------------------------------------------
// Tensor-core causal flash attention, bf16x3, online softmax, GQA group=4.
// 64x64 tiles, D=128, 128 threads (4 warps x 16 q-rows).
// Output written as bf16 hi/lo splits directly into proj GEMM input.
// ---------------------------------------------------------------------------
#define DS 136                       // padded smem row stride (bf16 elems)
#define FTB (64 * DS * 2)            // one 64x128 bf16 tile = 17408 B
#define FL_SMEM (6 * FTB)            // Qh Ql Kh Kl Vh Vl = 104448 B

__global__ void __launch_bounds__(128) flash_mma_kernel(
    const __nv_bfloat16* __restrict__ gqh, const __nv_bfloat16* __restrict__ gql,
    const __nv_bfloat16* __restrict__ gkh, const __nv_bfloat16* __restrict__ gkl,
    const __nv_bfloat16* __restrict__ gvh, const __nv_bfloat16* __restrict__ gvl,
    __nv_bfloat16* __restrict__ outh, __nv_bfloat16* __restrict__ outl)
{
    extern __shared__ char smem[];
    const uint32_t sb = smem_to_u32(smem);
    const uint32_t sQh = sb,           sQl = sb + FTB;
    const uint32_t sKh = sb + 2 * FTB, sKl = sb + 3 * FTB;
    const uint32_t sVh = sb + 4 * FTB, sVl = sb + 5 * FTB;

    const int qt = blockIdx.x;
    const int h  = blockIdx.y;
    const int b  = blockIdx.z;
    const int kvh = h >> 2;
    const int tid = threadIdx.x;
    const int wid = tid >> 5;
    const int lane = tid & 31;
    const int m0 = wid * 16;

    const __nv_bfloat16* Qh = gqh + ((size_t)(b * NH + h) * SEQ + (size_t)qt * 64) * HD;
    const __nv_bfloat16* Ql = gql + ((size_t)(b * NH + h) * SEQ + (size_t)qt * 64) * HD;
    const __nv_bfloat16* Kh = gkh + (size_t)(b * NKV + kvh) * SEQ * HD;
    const __nv_bfloat16* Kl = gkl + (size_t)(b * NKV + kvh) * SEQ * HD;
    const __nv_bfloat16* Vh = gvh + (size_t)(b * NKV + kvh) * SEQ * HD;
    const __nv_bfloat16* Vl = gvl + (size_t)(b * NKV + kvh) * SEQ * HD;

    auto loadtile = [&](uint32_t dst, const __nv_bfloat16* src) {
#pragma unroll
        for (int i = 0; i < 8; i++) {
            const int f = tid + i * 128;
            const int r = f >> 4, sg = f & 15;
            cpa16(dst + (uint32_t)(r * DS + sg * 8) * 2, src + (size_t)r * HD + sg * 8);
        }
    };

    // Q tiles once
    loadtile(sQh, Qh);
    loadtile(sQl, Ql);
    CP_COMMIT();

    float o[16][4];
#pragma unroll
    for (int i = 0; i < 16; i++)
#pragma unroll
        for (int j = 0; j < 4; j++) o[i][j] = 0.f;
    float mrow[2] = {-INFINITY, -INFINITY};
    float lrow[2] = {0.f, 0.f};

    // fragment index components
    const int a_r = lane & 15, a_c = (lane >> 4) * 8;
    const int b_r = lane & 7,  b_g = lane >> 3;
    const int b_jj = b_g >> 1, b_kk = (b_g & 1) * 8;
    const int qrow = lane >> 2;          // local row within 8 (quad)
    const int qcol = (lane & 3) * 2;

    for (int jt = 0; jt <= qt; jt++) {
        __syncthreads();                 // prior compute done with K/V smem
        loadtile(sKh, Kh + (size_t)jt * 64 * HD);
        loadtile(sKl, Kl + (size_t)jt * 64 * HD);
        loadtile(sVh, Vh + (size_t)jt * 64 * HD);
        loadtile(sVl, Vl + (size_t)jt * 64 * HD);
        CP_COMMIT();
        CP_WAIT0();
        __syncthreads();

        // ---- scores = Q K^T (bf16x3, fp32-exact) ----
        float sc[8][4];
#pragma unroll
        for (int i = 0; i < 8; i++)
#pragma unroll
            for (int j = 0; j < 4; j++) sc[i][j] = 0.f;

#pragma unroll
        for (int kb = 0; kb < 8; kb++) {
            const uint32_t aoff = (uint32_t)((m0 + a_r) * DS + kb * 16 + a_c) * 2;
            uint32_t ah0, ah1, ah2, ah3, al0, al1, al2, al3;
            ldsm_x4(ah0, ah1, ah2, ah3, sQh + aoff);
            ldsm_x4(al0, al1, al2, al3, sQl + aoff);
#pragma unroll
            for (int np = 0; np < 4; np++) {
                const uint32_t boff =
                    (uint32_t)(((np * 2 + b_jj) * 8 + b_r) * DS + kb * 16 + b_kk) * 2;
                uint32_t bh0, bh1, bh2, bh3, bl0, bl1, bl2, bl3;
                ldsm_x4(bh0, bh1, bh2, bh3, sKh + boff);
                ldsm_x4(bl0, bl1, bl2, bl3, sKl + boff);
                float* c0 = sc[np * 2];
                float* c1 = sc[np * 2 + 1];
                mma_bf16(c0, ah0, ah1, ah2, ah3, bh0, bh1);
                mma_bf16(c1, ah0, ah1, ah2, ah3, bh2, bh3);
                mma_bf16(c0, ah0, ah1, ah2, ah3, bl0, bl1);
                mma_bf16(c1, ah0, ah1, ah2, ah3, bl2, bl3);
                mma_bf16(c0, al0, al1, al2, al3, bh0, bh1);
                mma_bf16(c1, al0, al1, al2, al3, bh2, bh3);
            }
        }

        // ---- causal mask on diagonal tile ----
        if (jt == qt) {
            const int r0 = m0 + qrow, r1 = r0 + 8;
#pragma unroll
            for (int nt = 0; nt < 8; nt++) {
                const int col = nt * 8 + qcol;
                if (col > r0)     sc[nt][0] = -INFINITY;
                if (col + 1 > r0) sc[nt][1] = -INFINITY;
                if (col > r1)     sc[nt][2] = -INFINITY;
                if (col + 1 > r1) sc[nt][3] = -INFINITY;
            }
        }

        // ---- online softmax (rows r0, r1 per thread) ----
        float mx0 = -INFINITY, mx1 = -INFINITY;
#pragma unroll
        for (int nt = 0; nt < 8; nt++) {
            mx0 = fmaxf(mx0, fmaxf(sc[nt][0], sc[nt][1]));
            mx1 = fmaxf(mx1, fmaxf(sc[nt][2], sc[nt][3]));
        }
        mx0 = fmaxf(mx0, __shfl_xor_sync(0xffffffffu, mx0, 1));
        mx0 = fmaxf(mx0, __shfl_xor_sync(0xffffffffu, mx0, 2));
        mx1 = fmaxf(mx1, __shfl_xor_sync(0xffffffffu, mx1, 1));
        mx1 = fmaxf(mx1, __shfl_xor_sync(0xffffffffu, mx1, 2));
        const float mn0 = fmaxf(mrow[0], mx0);
        const float mn1 = fmaxf(mrow[1], mx1);
        const float cr0 = __expf(mrow[0] - mn0);
        const float cr1 = __expf(mrow[1] - mn1);
        mrow[0] = mn0; mrow[1] = mn1;

        float s0 = 0.f, s1 = 0.f;
#pragma unroll
        for (int nt = 0; nt < 8; nt++) {
            sc[nt][0] = __expf(sc[nt][0] - mn0); s0 += sc[nt][0];
            sc[nt][1] = __expf(sc[nt][1] - mn0); s0 += sc[nt][1];
            sc[nt][2] = __expf(sc[nt][2] - mn1); s1 += sc[nt][2];
            sc[nt][3] = __expf(sc[nt][3] - mn1); s1 += sc[nt][3];
        }
        s0 += __shfl_xor_sync(0xffffffffu, s0, 1);
        s0 += __shfl_xor_sync(0xffffffffu, s0, 2);
        s1 += __shfl_xor_sync(0xffffffffu, s1, 1);
        s1 += __shfl_xor_sync(0xffffffffu, s1, 2);
        lrow[0] = lrow[0] * cr0 + s0;
        lrow[1] = lrow[1] * cr1 + s1;

#pragma unroll
        for (int nt = 0; nt < 16; nt++) {
            o[nt][0] *= cr0; o[nt][1] *= cr0;
            o[nt][2] *= cr1; o[nt][3] *= cr1;
        }

        // ---- out += P V (P split hi/lo, V bf16x3) ----
#pragma unroll
        for (int kc = 0; kc < 4; kc++) {
            // P fragments: accumulator layout == A-operand layout
            const float p00 = sc[kc * 2][0],     p01 = sc[kc * 2][1];
            const float p10 = sc[kc * 2][2],     p11 = sc[kc * 2][3];
            const float p20 = sc[kc * 2 + 1][0], p21 = sc[kc * 2 + 1][1];
            const float p30 = sc[kc * 2 + 1][2], p31 = sc[kc * 2 + 1][3];
            const uint32_t ph0 = pack2_bf16(p00, p01);
            const uint32_t ph1 = pack2_bf16(p10, p11);
            const uint32_t ph2 = pack2_bf16(p20, p21);
            const uint32_t ph3 = pack2_bf16(p30, p31);
            __nv_bfloat162 t0 = *(__nv_bfloat162*)&ph0;
            __nv_bfloat162 t1 = *(__nv_bfloat162*)&ph1;
            __nv_bfloat162 t2 = *(__nv_bfloat162*)&ph2;
            __nv_bfloat162 t3 = *(__nv_bfloat162*)&ph3;
            const uint32_t pl0 = pack2_bf16(p00 - __low2float(t0), p01 - __high2float(t0));
            const uint32_t pl1 = pack2_bf16(p10 - __low2float(t1), p11 - __high2float(t1));
            const uint32_t pl2 = pack2_bf16(p20 - __low2float(t2), p21 - __high2float(t2));
            const uint32_t pl3 = pack2_bf16(p30 - __low2float(t3), p31 - __high2float(t3));

#pragma unroll
            for (int npair = 0; npair < 8; npair++) {
                const uint32_t voff =
                    (uint32_t)((kc * 16 + a_r) * DS + npair * 16 + a_c) * 2;
                uint32_t vh0, vh1, vh2, vh3, wl0, wl1, wl2, wl3;
                ldsm_x4_t(vh0, vh1, vh2, vh3, sVh + voff);
                ldsm_x4_t(wl0, wl1, wl2, wl3, sVl + voff);
                float* c0 = o[npair * 2];
                float* c1 = o[npair * 2 + 1];
                mma_bf16(c0, ph0, ph1, ph2, ph3, vh0, vh1);
                mma_bf16(c1, ph0, ph1, ph2, ph3, vh2, vh3);
                mma_bf16(c0, ph0, ph1, ph2, ph3, wl0, wl1);
                mma_bf16(c1, ph0, ph1, ph2, ph3, wl2, wl3);
                mma_bf16(c0, pl0, pl1, pl2, pl3, vh0, vh1);
                mma_bf16(c1, pl0, pl1, pl2, pl3, vh2, vh3);
            }
        }
    }

    // ---- epilogue: normalize, split to bf16 hi/lo, store ----
    const float iv0 = 1.f / lrow[0];
    const float iv1 = 1.f / lrow[1];
    const size_t t0 = (size_t)b * SEQ + (size_t)qt * 64 + m0 + qrow;
    const size_t t1 = t0 + 8;
#pragma unroll
    for (int nt = 0; nt < 16; nt++) {
        const int col = h * HD + nt * 8 + qcol;
        {
            const float f0 = o[nt][0] * iv0, f1 = o[nt][1] * iv0;
            const uint32_t hh = pack2_bf16(f0, f1);
            __nv_bfloat162 th = *(__nv_bfloat162*)&hh;
            const uint32_t ll = pack2_bf16(f0 - __low2float(th), f1 - __high2float(th));
            *(uint32_t*)(outh + t0 * HID + col) = hh;
            *(uint32_t*)(outl + t0 * HID + col) = ll;
        }
        {
            const float f0 = o[nt][2] * iv1, f1 = o[nt][3] * iv1;
            const uint32_t hh = pack2_bf16(f0, f1);
            __nv_bfloat162 th = *(__nv_bfloat162*)&hh;
            const uint32_t ll = pack2_bf16(f0 - __low2float(th), f1 - __high2float(th));
            *(uint32_t*)(outh + t1 * HID + col) = hh;
            *(uint32_t*)(outl + t1 * HID + col) = ll;
        }
    }
}

// ---------------------------------------------------------------------------
extern "C" void kernel_launch(void* const* d_in, const int* in_sizes, int n_in,
                              void* d_out, int out_size)
{
    const float* hidden    = (const float*)d_in[0];
    const int*   positions = (const int*)d_in[1];
    const float* wqkv      = (const float*)d_in[2];
    const float* qnw       = (const float*)d_in[3];
    const float* knw       = (const float*)d_in[4];
    const float* wo        = (const float*)d_in[5];
    float* out = (float*)d_out;

    float* qkv;
    __nv_bfloat16 *ahi, *alo, *whi, *wlo, *qh, *ql, *kh, *kl, *vh, *vl;
    cudaGetSymbolAddress((void**)&qkv, g_qkv);
    cudaGetSymbolAddress((void**)&ahi, g_ahi);
    cudaGetSymbolAddress((void**)&alo, g_alo);
    cudaGetSymbolAddress((void**)&whi, g_whi);
    cudaGetSymbolAddress((void**)&wlo, g_wlo);
    cudaGetSymbolAddress((void**)&qh, g_qh);
    cudaGetSymbolAddress((void**)&ql, g_ql);
    cudaGetSymbolAddress((void**)&kh, g_kh);
    cudaGetSymbolAddress((void**)&kl, g_kl);
    cudaGetSymbolAddress((void**)&vh, g_vh);
    cudaGetSymbolAddress((void**)&vl, g_vl);

    cudaFuncSetAttribute(gemm_bf16x3_kernel,
                         cudaFuncAttributeMaxDynamicSharedMemorySize, GEMM_SMEM);
    cudaFuncSetAttribute(flash_mma_kernel,
                         cudaFuncAttributeMaxDynamicSharedMemorySize, FL_SMEM);

    const size_t nA  = (size_t)MTOK * HID;
    const size_t nW1 = (size_t)QKVO * HID;

    // 1) split-convert hidden and wqkv
    conv_split_kernel<<<(unsigned)((nA / 4 + 255) / 256), 256>>>(hidden, ahi, alo, nA);
    conv_split_kernel<<<(unsigned)((nW1 / 4 + 255) / 256), 256>>>(wqkv, whi, wlo, nW1);

    // 2) QKV projection
    dim3 g1(QKVO / 128, MTOK / 128);
    gemm_bf16x3_kernel<<<g1, 256, GEMM_SMEM>>>(ahi, alo, whi, wlo, qkv, MTOK, QKVO, HID);

    // 3) RMSNorm + RoPE + split to bf16 hi/lo (scale folded into Q)
    dim3 g2(MTOK, NH + 2 * NKV);
    norm_rope_split_kernel<<<g2, 128>>>(qkv, positions, qnw, knw,
                                        qh, ql, kh, kl, vh, vl);

    // 4) Tensor-core causal flash attention -> attn splits (reuse ahi/alo)
    dim3 g3(SEQ / 64, NH, NB);
    flash_mma_kernel<<<g3, 128, FL_SMEM>>>(qh, ql, kh, kl, vh, vl, ahi, alo);

    // 5) convert wo, output projection
    conv_split_kernel<<<(unsigned)((nA / 4 + 255) / 256), 256>>>(wo, whi, wlo, nA);
    dim3 g4(HID / 128, MTOK / 128);
    gemm_bf16x3_kernel<<<g4, 256, GEMM_SMEM>>>(ahi, alo, whi, wlo, out, MTOK, HID, HID);
}

// round 6
// speedup vs baseline: 4.1813x; 1.6673x over previous
#include <cuda_runtime.h>
#include <cuda_bf16.h>
#include <math.h>
#include <stdint.h>

// Problem constants
#define NB   2
#define SEQ  2048
#define HID  4096
#define NH   32
#define NKV  8
#define HD   128
#define QKVO ((NH + 2*NKV)*HD)   // 6144
#define MTOK (NB*SEQ)            // 4096

// Scratch (no cudaMalloc allowed)
__device__ float g_qkv[(size_t)MTOK * QKVO];
__device__ __nv_bfloat16 g_ahi[(size_t)MTOK * HID];
__device__ __nv_bfloat16 g_alo[(size_t)MTOK * HID];
__device__ __nv_bfloat16 g_whi[(size_t)QKVO * HID];
__device__ __nv_bfloat16 g_wlo[(size_t)QKVO * HID];
__device__ __nv_bfloat16 g_qh[(size_t)NB * NH * SEQ * HD];
__device__ __nv_bfloat16 g_ql[(size_t)NB * NH * SEQ * HD];
__device__ __nv_bfloat16 g_kh[(size_t)NB * NKV * SEQ * HD];
__device__ __nv_bfloat16 g_kl[(size_t)NB * NKV * SEQ * HD];
__device__ __nv_bfloat16 g_vh[(size_t)NB * NKV * SEQ * HD];
__device__ __nv_bfloat16 g_vl[(size_t)NB * NKV * SEQ * HD];
__device__ float2 g_rope[(size_t)SEQ * 64];   // (cos, sin) per (s, i)

// ===========================================================================
// Low-level helpers (sm_80-baseline ISA: ldmatrix / mma.sync / cp.async)
// ===========================================================================
__device__ __forceinline__ uint32_t smem_to_u32(const void* p) {
    uint32_t a;
    asm("{ .reg .u64 t; cvta.to.shared.u64 t, %1; cvt.u32.u64 %0, t; }" : "=r"(a) : "l"(p));
    return a;
}
__device__ __forceinline__ void ldsm_x4(uint32_t& r0, uint32_t& r1, uint32_t& r2,
                                        uint32_t& r3, uint32_t addr) {
    asm volatile("ldmatrix.sync.aligned.m8n8.x4.shared.b16 {%0,%1,%2,%3}, [%4];"
                 : "=r"(r0), "=r"(r1), "=r"(r2), "=r"(r3) : "r"(addr));
}
__device__ __forceinline__ void ldsm_x4_t(uint32_t& r0, uint32_t& r1, uint32_t& r2,
                                          uint32_t& r3, uint32_t addr) {
    asm volatile("ldmatrix.sync.aligned.m8n8.x4.trans.shared.b16 {%0,%1,%2,%3}, [%4];"
                 : "=r"(r0), "=r"(r1), "=r"(r2), "=r"(r3) : "r"(addr));
}
__device__ __forceinline__ void mma_bf16(float* c, uint32_t a0, uint32_t a1,
                                         uint32_t a2, uint32_t a3,
                                         uint32_t b0, uint32_t b1) {
    asm volatile(
        "mma.sync.aligned.m16n8k16.row.col.f32.bf16.bf16.f32 "
        "{%0,%1,%2,%3}, {%4,%5,%6,%7}, {%8,%9}, {%0,%1,%2,%3};"
        : "+f"(c[0]), "+f"(c[1]), "+f"(c[2]), "+f"(c[3])
        : "r"(a0), "r"(a1), "r"(a2), "r"(a3), "r"(b0), "r"(b1));
}
__device__ __forceinline__ void cpa16(uint32_t dst, const void* src) {
    asm volatile("cp.async.cg.shared.global [%0], [%1], 16;" :: "r"(dst), "l"(src));
}
#define CP_COMMIT() asm volatile("cp.async.commit_group;" ::: "memory")
#define CP_WAIT0()  asm volatile("cp.async.wait_group 0;" ::: "memory")
#define CP_WAIT1()  asm volatile("cp.async.wait_group 1;" ::: "memory")

__device__ __forceinline__ uint32_t pack2_bf16(float a, float b) {
    __nv_bfloat162 t = __floats2bfloat162_rn(a, b);
    return *reinterpret_cast<uint32_t*>(&t);
}

// ===========================================================================
// RoPE table: (cos, sin) per (s, i) computed in fp64 once
// ===========================================================================
__global__ void __launch_bounds__(256) rope_table_kernel(const int* __restrict__ positions)
{
    const int idx = blockIdx.x * 256 + threadIdx.x;
    if (idx >= SEQ * 64) return;
    const int s = idx >> 6, i = idx & 63;
    const int pos = positions[s];
    const double inv = exp(-(double)i * (9.210340371976184 / 64.0));
    double sd, cd;
    sincos((double)pos * inv, &sd, &cd);
    g_rope[idx] = make_float2((float)cd, (float)sd);
}

// ===========================================================================
// Split conversion: fp32 -> (bf16 hi, bf16 lo)
// ===========================================================================
__global__ void __launch_bounds__(256) conv_split_kernel(
    const float* __restrict__ x, __nv_bfloat16* __restrict__ hi,
    __nv_bfloat16* __restrict__ lo, size_t n)
{
    size_t i = ((size_t)blockIdx.x * 256 + threadIdx.x) * 4;
    if (i >= n) return;
    float4 v = *(const float4*)(x + i);
    float f[4] = {v.x, v.y, v.z, v.w};
    __nv_bfloat16 h[4], l[4];
#pragma unroll
    for (int j = 0; j < 4; j++) {
        h[j] = __float2bfloat16(f[j]);
        l[j] = __float2bfloat16(f[j] - __bfloat162float(h[j]));
    }
    *(uint2*)(hi + i) = *(uint2*)h;
    *(uint2*)(lo + i) = *(uint2*)l;
}

// ===========================================================================
// bf16x3 GEMM-NT via mma.sync, XOR-swizzled smem, 3-stage cp.async pipeline.
// CTA 128x128, K-chunk 32, 256 threads (8 warps 2x4).
// Tile: 128 rows x 64B (32 bf16); swizzle: seg' = seg ^ ((row>>1)&3).
// ===========================================================================
#define GK 32
#define GTILE 8192                   // 128*64 B
#define GSTAGE (4 * GTILE)           // Ahi, Alo, Bhi, Blo = 32768
#define GEMM_SMEM (3 * GSTAGE)       // 98304

__device__ __forceinline__ uint32_t gsw(int row, int seg) {
    return (uint32_t)(row * 64 + ((seg ^ (row >> 1)) & 3) * 16);
}

__global__ void __launch_bounds__(256, 2) gemm_bf16x3_kernel(
    const __nv_bfloat16* __restrict__ Ah, const __nv_bfloat16* __restrict__ Al,
    const __nv_bfloat16* __restrict__ Bh, const __nv_bfloat16* __restrict__ Bl,
    float* __restrict__ C, int M, int N, int K)
{
    extern __shared__ char smem[];
    const uint32_t sb = smem_to_u32(smem);
    const int tid  = threadIdx.x;
    const int wid  = tid >> 5;
    const int lane = tid & 31;
    const int warp_m = wid >> 2;
    const int warp_n = wid & 3;
    const int bm = blockIdx.y * 128;
    const int bn = blockIdx.x * 128;

    const __nv_bfloat16* srcs[4] = {
        Ah + (size_t)bm * K, Al + (size_t)bm * K,
        Bh + (size_t)bn * K, Bl + (size_t)bn * K };

    float acc[4][4][4];
#pragma unroll
    for (int i = 0; i < 4; i++)
#pragma unroll
        for (int j = 0; j < 4; j++)
#pragma unroll
            for (int r = 0; r < 4; r++) acc[i][j][r] = 0.f;

    auto prefetch = [&](int k0, int s) {
        const uint32_t base = sb + s * GSTAGE;
#pragma unroll
        for (int t = 0; t < 4; t++) {
            const __nv_bfloat16* src = srcs[t];
#pragma unroll
            for (int i = 0; i < 2; i++) {
                const int f = tid + i * 256;        // 0..511
                const int r = f >> 2, sg = f & 3;
                cpa16(base + t * GTILE + gsw(r, sg),
                      src + (size_t)r * K + k0 + sg * 8);
            }
        }
        CP_COMMIT();
    };

    const int NC = K / GK;
    prefetch(0, 0);
    prefetch(GK, 1);

    const int a_r = lane & 15;
    const int a_h = lane >> 4;          // 16B half within 32B k-step
    const int b_g = lane >> 3;
    const int b_r = lane & 7;
    const int b_jj = b_g >> 1;
    const int b_h = b_g & 1;

    for (int c = 0; c < NC; c++) {
        if (c + 1 < NC) { CP_WAIT1(); } else { CP_WAIT0(); }
        __syncthreads();
        if (c + 2 < NC) prefetch((c + 2) * GK, (c + 2) % 3);

        const uint32_t base = sb + (c % 3) * GSTAGE;
#pragma unroll
        for (int ks = 0; ks < 2; ks++) {
            uint32_t ah[4][4], al[4][4];
#pragma unroll
            for (int mt = 0; mt < 4; mt++) {
                const int row = warp_m * 64 + mt * 16 + a_r;
                const uint32_t off = gsw(row, ks * 2 + a_h);
                ldsm_x4(ah[mt][0], ah[mt][1], ah[mt][2], ah[mt][3], base + off);
                ldsm_x4(al[mt][0], al[mt][1], al[mt][2], al[mt][3],
                        base + GTILE + off);
            }
#pragma unroll
            for (int jp = 0; jp < 2; jp++) {
                const int rowb = warp_n * 32 + (jp * 2 + b_jj) * 8 + b_r;
                const uint32_t boff = gsw(rowb, ks * 2 + b_h);
                uint32_t bh0, bh1, bh2, bh3, bl0, bl1, bl2, bl3;
                ldsm_x4(bh0, bh1, bh2, bh3, base + 2 * GTILE + boff);
                ldsm_x4(bl0, bl1, bl2, bl3, base + 3 * GTILE + boff);
#pragma unroll
                for (int mt = 0; mt < 4; mt++) {
                    float* c0 = acc[mt][jp * 2];
                    float* c1 = acc[mt][jp * 2 + 1];
                    mma_bf16(c0, ah[mt][0], ah[mt][1], ah[mt][2], ah[mt][3], bh0, bh1);
                    mma_bf16(c1, ah[mt][0], ah[mt][1], ah[mt][2], ah[mt][3], bh2, bh3);
                    mma_bf16(c0, ah[mt][0], ah[mt][1], ah[mt][2], ah[mt][3], bl0, bl1);
                    mma_bf16(c1, ah[mt][0], ah[mt][1], ah[mt][2], ah[mt][3], bl2, bl3);
                    mma_bf16(c0, al[mt][0], al[mt][1], al[mt][2], al[mt][3], bh0, bh1);
                    mma_bf16(c1, al[mt][0], al[mt][1], al[mt][2], al[mt][3], bh2, bh3);
                }
            }
        }
    }

#pragma unroll
    for (int mt = 0; mt < 4; mt++) {
        const int row = bm + warp_m * 64 + mt * 16 + (lane >> 2);
#pragma unroll
        for (int nt = 0; nt < 4; nt++) {
            const int col = bn + warp_n * 32 + nt * 8 + (lane & 3) * 2;
            float* cp0 = C + (size_t)row * N + col;
            float* cp1 = C + (size_t)(row + 8) * N + col;
            *(float2*)cp0 = make_float2(acc[mt][nt][0], acc[mt][nt][1]);
            *(float2*)cp1 = make_float2(acc[mt][nt][2], acc[mt][nt][3]);
        }
    }
}

// ---------------------------------------------------------------------------
// RMSNorm + RoPE (table) -> pre-split bf16 hi/lo head-major q/k/v.
// ---------------------------------------------------------------------------
__global__ void __launch_bounds__(128) norm_rope_split_kernel(
    const float* __restrict__ qkv,
    const float* __restrict__ qw, const float* __restrict__ kw,
    __nv_bfloat16* __restrict__ qh, __nv_bfloat16* __restrict__ ql,
    __nv_bfloat16* __restrict__ kh, __nv_bfloat16* __restrict__ kl,
    __nv_bfloat16* __restrict__ vh, __nv_bfloat16* __restrict__ vl)
{
    const int token = blockIdx.x;
    const int b = token / SEQ;
    const int s = token - b * SEQ;
    const int head = blockIdx.y;
    const int d = threadIdx.x;

    if (head >= NH + NKV) {      // V: plain split
        const int kvh = head - NH - NKV;
        float x = qkv[(size_t)token * QKVO + (size_t)(NH + NKV) * HD + kvh * HD + d];
        const size_t o = ((size_t)(b * NKV + kvh) * SEQ + s) * HD + d;
        __nv_bfloat16 h = __float2bfloat16(x);
        vh[o] = h;
        vl[o] = __float2bfloat16(x - __bfloat162float(h));
        return;
    }

    const bool is_q = head < NH;
    const float* src = qkv + (size_t)token * QKVO
                     + (is_q ? (size_t)head * HD : (size_t)NH * HD + (size_t)(head - NH) * HD);
    float x = src[d];

    __shared__ float red[4];
    __shared__ float ys[HD];

    float sq = x * x;
#pragma unroll
    for (int o = 16; o > 0; o >>= 1) sq += __shfl_xor_sync(0xffffffffu, sq, o);
    if ((d & 31) == 0) red[d >> 5] = sq;
    __syncthreads();
    const float var = (red[0] + red[1] + red[2] + red[3]) * (1.0f / HD);
    const float rn = rsqrtf(var + 1e-6f);
    const float w = is_q ? qw[d] : kw[d];
    ys[d] = x * rn * w;
    __syncthreads();

    const int i = d & 63;
    const float2 cs = g_rope[(size_t)s * 64 + i];
    const float c = cs.x, sn = cs.y;

    const float x1 = ys[i];
    const float x2 = ys[i + 64];
    float outv = (d < 64) ? (x1 * c - x2 * sn) : (x2 * c + x1 * sn);
    if (is_q) outv *= 0.08838834764831843f;

    __nv_bfloat16 h = __float2bfloat16(outv);
    __nv_bfloat16 l = __float2bfloat16(outv - __bfloat162float(h));

    if (is_q) {
        const size_t o = ((size_t)(b * NH + head) * SEQ + s) * HD + d;
        qh[o] = h; ql[o] = l;
    } else {
        const size_t o = ((size_t)(b * NKV + (head - NH)) * SEQ + s) * HD + d;
        kh[o] = h; kl[o] = l;
    }
}

// ---------------------------------------------------------------------------
// Tensor-core causal flash attention, bf16x3, Q fragments register-resident.
// 64x64 tiles, D=128, 128 threads (4 warps x 16 q-rows).
// ---------------------------------------------------------------------------
#define DS 136
#define FTB (64 * DS * 2)            // 17408
#define FL_SMEM (4 * FTB)            // Kh Kl Vh Vl = 69632

__global__ void __launch_bounds__(128) flash_mma_kernel(
    const __nv_bfloat16* __restrict__ gqh, const __nv_bfloat16* __restrict__ gql,
    const __nv_bfloat16* __restrict__ gkh, const __nv_bfloat16* __restrict__ gkl,
    const __nv_bfloat16* __restrict__ gvh, const __nv_bfloat16* __restrict__ gvl,
    __nv_bfloat16* __restrict__ outh, __nv_bfloat16* __restrict__ outl)
{
    extern __shared__ char smem[];
    const uint32_t sb = smem_to_u32(smem);
    const uint32_t sKh = sb,           sKl = sb + FTB;
    const uint32_t sVh = sb + 2 * FTB, sVl = sb + 3 * FTB;

    const int qt = blockIdx.x;
    const int h  = blockIdx.y;
    const int b  = blockIdx.z;
    const int kvh = h >> 2;
    const int tid = threadIdx.x;
    const int wid = tid >> 5;
    const int lane = tid & 31;
    const int m0 = wid * 16;

    const __nv_bfloat16* Qh = gqh + ((size_t)(b * NH + h) * SEQ + (size_t)qt * 64) * HD;
    const __nv_bfloat16* Ql = gql + ((size_t)(b * NH + h) * SEQ + (size_t)qt * 64) * HD;
    const __nv_bfloat16* Kh = gkh + (size_t)(b * NKV + kvh) * SEQ * HD;
    const __nv_bfloat16* Kl = gkl + (size_t)(b * NKV + kvh) * SEQ * HD;
    const __nv_bfloat16* Vh = gvh + (size_t)(b * NKV + kvh) * SEQ * HD;
    const __nv_bfloat16* Vl = gvl + (size_t)(b * NKV + kvh) * SEQ * HD;

    auto loadtile = [&](uint32_t dst, const __nv_bfloat16* src) {
#pragma unroll
        for (int i = 0; i < 8; i++) {
            const int f = tid + i * 128;
            const int r = f >> 4, sg = f & 15;
            cpa16(dst + (uint32_t)(r * DS + sg * 8) * 2, src + (size_t)r * HD + sg * 8);
        }
    };

    const int a_r = lane & 15, a_c = (lane >> 4) * 8;
    const int b_r = lane & 7,  b_g = lane >> 3;
    const int b_jj = b_g >> 1, b_kk = (b_g & 1) * 8;
    const int qrow = lane >> 2;
    const int qcol = (lane & 3) * 2;

    // ---- stage Q through smem once, hoist fragments to registers ----
    loadtile(sKh, Qh);
    loadtile(sKl, Ql);
    CP_COMMIT();
    CP_WAIT0();
    __syncthreads();
    uint32_t qfh[8][4], qfl[8][4];
#pragma unroll
    for (int kb = 0; kb < 8; kb++) {
        const uint32_t aoff = (uint32_t)((m0 + a_r) * DS + kb * 16 + a_c) * 2;
        ldsm_x4(qfh[kb][0], qfh[kb][1], qfh[kb][2], qfh[kb][3], sKh + aoff);
        ldsm_x4(qfl[kb][0], qfl[kb][1], qfl[kb][2], qfl[kb][3], sKl + aoff);
    }
    __syncthreads();

    float o[16][4];
#pragma unroll
    for (int i = 0; i < 16; i++)
#pragma unroll
        for (int j = 0; j < 4; j++) o[i][j] = 0.f;
    float mrow[2] = {-INFINITY, -INFINITY};
    float lrow[2] = {0.f, 0.f};

    for (int jt = 0; jt <= qt; jt++) {
        loadtile(sKh, Kh + (size_t)jt * 64 * HD);
        loadtile(sKl, Kl + (size_t)jt * 64 * HD);
        loadtile(sVh, Vh + (size_t)jt * 64 * HD);
        loadtile(sVl, Vl + (size_t)jt * 64 * HD);
        CP_COMMIT();
        CP_WAIT0();
        __syncthreads();

        // ---- scores = Q K^T (bf16x3, fp32-exact) ----
        float sc[8][4];
#pragma unroll
        for (int i = 0; i < 8; i++)
#pragma unroll
            for (int j = 0; j < 4; j++) sc[i][j] = 0.f;

#pragma unroll
        for (int kb = 0; kb < 8; kb++) {
#pragma unroll
            for (int np = 0; np < 4; np++) {
                const uint32_t boff =
                    (uint32_t)(((np * 2 + b_jj) * 8 + b_r) * DS + kb * 16 + b_kk) * 2;
                uint32_t bh0, bh1, bh2, bh3, bl0, bl1, bl2, bl3;
                ldsm_x4(bh0, bh1, bh2, bh3, sKh + boff);
                ldsm_x4(bl0, bl1, bl2, bl3, sKl + boff);
                float* c0 = sc[np * 2];
                float* c1 = sc[np * 2 + 1];
                mma_bf16(c0, qfh[kb][0], qfh[kb][1], qfh[kb][2], qfh[kb][3], bh0, bh1);
                mma_bf16(c1, qfh[kb][0], qfh[kb][1], qfh[kb][2], qfh[kb][3], bh2, bh3);
                mma_bf16(c0, qfh[kb][0], qfh[kb][1], qfh[kb][2], qfh[kb][3], bl0, bl1);
                mma_bf16(c1, qfh[kb][0], qfh[kb][1], qfh[kb][2], qfh[kb][3], bl2, bl3);
                mma_bf16(c0, qfl[kb][0], qfl[kb][1], qfl[kb][2], qfl[kb][3], bh0, bh1);
                mma_bf16(c1, qfl[kb][0], qfl[kb][1], qfl[kb][2], qfl[kb][3], bh2, bh3);
            }
        }

        // ---- causal mask on diagonal tile ----
        if (jt == qt) {
            const int r0 = m0 + qrow, r1 = r0 + 8;
#pragma unroll
            for (int nt = 0; nt < 8; nt++) {
                const int col = nt * 8 + qcol;
                if (col > r0)     sc[nt][0] = -INFINITY;
                if (col + 1 > r0) sc[nt][1] = -INFINITY;
                if (col > r1)     sc[nt][2] = -INFINITY;
                if (col + 1 > r1) sc[nt][3] = -INFINITY;
            }
        }

        // ---- online softmax ----
        float mx0 = -INFINITY, mx1 = -INFINITY;
#pragma unroll
        for (int nt = 0; nt < 8; nt++) {
            mx0 = fmaxf(mx0, fmaxf(sc[nt][0], sc[nt][1]));
            mx1 = fmaxf(mx1, fmaxf(sc[nt][2], sc[nt][3]));
        }
        mx0 = fmaxf(mx0, __shfl_xor_sync(0xffffffffu, mx0, 1));
        mx0 = fmaxf(mx0, __shfl_xor_sync(0xffffffffu, mx0, 2));
        mx1 = fmaxf(mx1, __shfl_xor_sync(0xffffffffu, mx1, 1));
        mx1 = fmaxf(mx1, __shfl_xor_sync(0xffffffffu, mx1, 2));
        const float mn0 = fmaxf(mrow[0], mx0);
        const float mn1 = fmaxf(mrow[1], mx1);
        const float cr0 = __expf(mrow[0] - mn0);
        const float cr1 = __expf(mrow[1] - mn1);
        mrow[0] = mn0; mrow[1] = mn1;

        float s0 = 0.f, s1 = 0.f;
#pragma unroll
        for (int nt = 0; nt < 8; nt++) {
            sc[nt][0] = __expf(sc[nt][0] - mn0); s0 += sc[nt][0];
            sc[nt][1] = __expf(sc[nt][1] - mn0); s0 += sc[nt][1];
            sc[nt][2] = __expf(sc[nt][2] - mn1); s1 += sc[nt][2];
            sc[nt][3] = __expf(sc[nt][3] - mn1); s1 += sc[nt][3];
        }
        s0 += __shfl_xor_sync(0xffffffffu, s0, 1);
        s0 += __shfl_xor_sync(0xffffffffu, s0, 2);
        s1 += __shfl_xor_sync(0xffffffffu, s1, 1);
        s1 += __shfl_xor_sync(0xffffffffu, s1, 2);
        lrow[0] = lrow[0] * cr0 + s0;
        lrow[1] = lrow[1] * cr1 + s1;

#pragma unroll
        for (int nt = 0; nt < 16; nt++) {
            o[nt][0] *= cr0; o[nt][1] *= cr0;
            o[nt][2] *= cr1; o[nt][3] *= cr1;
        }

        // ---- out += P V (P split hi/lo, V bf16x3) ----
#pragma unroll
        for (int kc = 0; kc < 4; kc++) {
            const float p00 = sc[kc * 2][0],     p01 = sc[kc * 2][1];
            const float p10 = sc[kc * 2][2],     p11 = sc[kc * 2][3];
            const float p20 = sc[kc * 2 + 1][0], p21 = sc[kc * 2 + 1][1];
            const float p30 = sc[kc * 2 + 1][2], p31 = sc[kc * 2 + 1][3];
            const uint32_t ph0 = pack2_bf16(p00, p01);
            const uint32_t ph1 = pack2_bf16(p10, p11);
            const uint32_t ph2 = pack2_bf16(p20, p21);
            const uint32_t ph3 = pack2_bf16(p30, p31);
            __nv_bfloat162 t0 = *(__nv_bfloat162*)&ph0;
            __nv_bfloat162 t1 = *(__nv_bfloat162*)&ph1;
            __nv_bfloat162 t2 = *(__nv_bfloat162*)&ph2;
            __nv_bfloat162 t3 = *(__nv_bfloat162*)&ph3;
            const uint32_t pl0 = pack2_bf16(p00 - __low2float(t0), p01 - __high2float(t0));
            const uint32_t pl1 = pack2_bf16(p10 - __low2float(t1), p11 - __high2float(t1));
            const uint32_t pl2 = pack2_bf16(p20 - __low2float(t2), p21 - __high2float(t2));
            const uint32_t pl3 = pack2_bf16(p30 - __low2float(t3), p31 - __high2float(t3));

#pragma unroll
            for (int npair = 0; npair < 8; npair++) {
                const uint32_t voff =
                    (uint32_t)((kc * 16 + a_r) * DS + npair * 16 + a_c) * 2;
                uint32_t vh0, vh1, vh2, vh3, wl0, wl1, wl2, wl3;
                ldsm_x4_t(vh0, vh1, vh2, vh3, sVh + voff);
                ldsm_x4_t(wl0, wl1, wl2, wl3, sVl + voff);
                float* c0 = o[npair * 2];
                float* c1 = o[npair * 2 + 1];
                mma_bf16(c0, ph0, ph1, ph2, ph3, vh0, vh1);
                mma_bf16(c1, ph0, ph1, ph2, ph3, vh2, vh3);
                mma_bf16(c0, ph0, ph1, ph2, ph3, wl0, wl1);
                mma_bf16(c1, ph0, ph1, ph2, ph3, wl2, wl3);
                mma_bf16(c0, pl0, pl1, pl2, pl3, vh0, vh1);
                mma_bf16(c1, pl0, pl1, pl2, pl3, vh2, vh3);
            }
        }
        __syncthreads();   // compute done before next iteration's loads overwrite
    }

    // ---- epilogue: normalize, split to bf16 hi/lo, store ----
    const float iv0 = 1.f / lrow[0];
    const float iv1 = 1.f / lrow[1];
    const size_t t0 = (size_t)b * SEQ + (size_t)qt * 64 + m0 + qrow;
    const size_t t1 = t0 + 8;
#pragma unroll
    for (int nt = 0; nt < 16; nt++) {
        const int col = h * HD + nt * 8 + qcol;
        {
            const float f0 = o[nt][0] * iv0, f1 = o[nt][1] * iv0;
            const uint32_t hh = pack2_bf16(f0, f1);
            __nv_bfloat162 th = *(__nv_bfloat162*)&hh;
            const uint32_t ll = pack2_bf16(f0 - __low2float(th), f1 - __high2float(th));
            *(uint32_t*)(outh + t0 * HID + col) = hh;
            *(uint32_t*)(outl + t0 * HID + col) = ll;
        }
        {
            const float f0 = o[nt][2] * iv1, f1 = o[nt][3] * iv1;
            const uint32_t hh = pack2_bf16(f0, f1);
            __nv_bfloat162 th = *(__nv_bfloat162*)&hh;
            const uint32_t ll = pack2_bf16(f0 - __low2float(th), f1 - __high2float(th));
            *(uint32_t*)(outh + t1 * HID + col) = hh;
            *(uint32_t*)(outl + t1 * HID + col) = ll;
        }
    }
}

// ---------------------------------------------------------------------------
extern "C" void kernel_launch(void* const* d_in, const int* in_sizes, int n_in,
                              void* d_out, int out_size)
{
    const float* hidden    = (const float*)d_in[0];
    const int*   positions = (const int*)d_in[1];
    const float* wqkv      = (const float*)d_in[2];
    const float* qnw       = (const float*)d_in[3];
    const float* knw       = (const float*)d_in[4];
    const float* wo        = (const float*)d_in[5];
    float* out = (float*)d_out;

    float* qkv;
    __nv_bfloat16 *ahi, *alo, *whi, *wlo, *qh, *ql, *kh, *kl, *vh, *vl;
    cudaGetSymbolAddress((void**)&qkv, g_qkv);
    cudaGetSymbolAddress((void**)&ahi, g_ahi);
    cudaGetSymbolAddress((void**)&alo, g_alo);
    cudaGetSymbolAddress((void**)&whi, g_whi);
    cudaGetSymbolAddress((void**)&wlo, g_wlo);
    cudaGetSymbolAddress((void**)&qh, g_qh);
    cudaGetSymbolAddress((void**)&ql, g_ql);
    cudaGetSymbolAddress((void**)&kh, g_kh);
    cudaGetSymbolAddress((void**)&kl, g_kl);
    cudaGetSymbolAddress((void**)&vh, g_vh);
    cudaGetSymbolAddress((void**)&vl, g_vl);

    cudaFuncSetAttribute(gemm_bf16x3_kernel,
                         cudaFuncAttributeMaxDynamicSharedMemorySize, GEMM_SMEM);
    cudaFuncSetAttribute(flash_mma_kernel,
                         cudaFuncAttributeMaxDynamicSharedMemorySize, FL_SMEM);

    const size_t nA  = (size_t)MTOK * HID;
    const size_t nW1 = (size_t)QKVO * HID;

    // 0) RoPE table (fp64 accuracy, tiny)
    rope_table_kernel<<<(SEQ * 64 + 255) / 256, 256>>>(positions);

    // 1) split-convert hidden and wqkv
    conv_split_kernel<<<(unsigned)((nA / 4 + 255) / 256), 256>>>(hidden, ahi, alo, nA);
    conv_split_kernel<<<(unsigned)((nW1 / 4 + 255) / 256), 256>>>(wqkv, whi, wlo, nW1);

    // 2) QKV projection
    dim3 g1(QKVO / 128, MTOK / 128);
    gemm_bf16x3_kernel<<<g1, 256, GEMM_SMEM>>>(ahi, alo, whi, wlo, qkv, MTOK, QKVO, HID);

    // 3) RMSNorm + RoPE + split to bf16 hi/lo (scale folded into Q)
    dim3 g2(MTOK, NH + 2 * NKV);
    norm_rope_split_kernel<<<g2, 128>>>(qkv, qnw, knw, qh, ql, kh, kl, vh, vl);

    // 4) Tensor-core causal flash attention -> attn splits (reuse ahi/alo)
    dim3 g3(SEQ / 64, NH, NB);
    flash_mma_kernel<<<g3, 128, FL_SMEM>>>(qh, ql, kh, kl, vh, vl, ahi, alo);

    // 5) convert wo, output projection
    conv_split_kernel<<<(unsigned)((nA / 4 + 255) / 256), 256>>>(wo, whi, wlo, nA);
    dim3 g4(HID / 128, MTOK / 128);
    gemm_bf16x3_kernel<<<g4, 256, GEMM_SMEM>>>(ahi, alo, whi, wlo, out, MTOK, HID, HID);
}